// round 10
// baseline (speedup 1.0000x reference)
#include <cuda_runtime.h>
#include <cuda_fp16.h>
#include <cstdint>

// Problem constants
#define NB    32
#define CLOC  512
#define HW2   196
#define NHW   6272
#define DGLB  2048
#define HIDN  256
#define EPSC  1e-10f

// Scratch (device globals; no allocation allowed)
__device__ float    g_hloc[NHW * HIDN];      // 6.4 MB
__device__ float    g_hglb[NB * HIDN];
__device__ float    g_scores[NB * NHW];      // 0.8 MB
// W2 in mma-fragment order: pair id = ((ks*4 + nw)*8 + nt)*32 + lane,
// pair = (b0, b1) for thread `lane` of warp-n-block nw, n-tile nt, k-step ks.
__device__ uint2    g_W2f[16 * 4 * 8 * 32];  // 128 KB

// ---------------------------------------------------------------------------
// helpers
// ---------------------------------------------------------------------------
__device__ __forceinline__ void mma16(float* c, const uint32_t* a,
                                      uint32_t b0, uint32_t b1) {
    asm volatile(
        "mma.sync.aligned.m16n8k16.row.col.f32.f16.f16.f32 "
        "{%0,%1,%2,%3}, {%4,%5,%6,%7}, {%8,%9}, {%0,%1,%2,%3};"
        : "+f"(c[0]), "+f"(c[1]), "+f"(c[2]), "+f"(c[3])
        : "r"(a[0]), "r"(a[1]), "r"(a[2]), "r"(a[3]), "r"(b0), "r"(b1));
}
__device__ __forceinline__ uint32_t smem_u32(const void* p) {
    uint32_t a;
    asm("{ .reg .u64 t; cvta.to.shared.u64 t, %1; cvt.u32.u64 %0, t; }" : "=r"(a) : "l"(p));
    return a;
}
__device__ __forceinline__ void cpa16(uint32_t dst, const void* src) {
    asm volatile("cp.async.ca.shared.global [%0], [%1], 16;" :: "r"(dst), "l"(src));
}
#define CPA_COMMIT() asm volatile("cp.async.commit_group;" ::: "memory")
#define CPA_WAIT0()  asm volatile("cp.async.wait_group 0;" ::: "memory")

// ---------------------------------------------------------------------------
// prep: blocks 0..31 -> h_glb (K-split x4, 1024 thr);
//       blocks 32..39 -> pack W2 into fragment order (fp16 pairs)
// ---------------------------------------------------------------------------
__global__ __launch_bounds__(1024) void prep_kernel(const float* __restrict__ gf,
                                                    const float* __restrict__ W1,
                                                    const float* __restrict__ b1,
                                                    const float* __restrict__ W2) {
    const int tid = threadIdx.x;
    if (blockIdx.x < NB) {
        __shared__ float red[1024];
        const int i  = blockIdx.x;
        const int o  = tid & 255;
        const int kq = tid >> 8;                 // 0..3
        const float* g = gf + i * DGLB + kq * 512;
        const float* w = W1 + (long)(kq * 512) * HIDN + o;
        float s0 = 0.f, s1 = 0.f;
        #pragma unroll 8
        for (int k = 0; k < 512; k += 2) {
            s0 += g[k]     * w[(long)k * HIDN];
            s1 += g[k + 1] * w[(long)(k + 1) * HIDN];
        }
        red[tid] = s0 + s1;
        __syncthreads();
        if (tid < 256)
            g_hglb[i * HIDN + o] = red[tid] + red[tid + 256] + red[tid + 512]
                                 + red[tid + 768] + b1[o];
    } else {
        // fragment-order pack: 16384 pairs total, 2 per thread
        const int pid0 = ((blockIdx.x - NB) * 1024 + tid) * 2;
        #pragma unroll
        for (int q = 0; q < 2; q++) {
            int id   = pid0 + q;
            int lane = id & 31;
            int nt   = (id >> 5) & 7;
            int nwp  = (id >> 8) & 3;
            int ks   = id >> 10;
            int gq   = lane >> 2, tg = lane & 3;
            int n    = nwp * 64 + nt * 8 + gq;
            int k0   = ks * 16 + 2 * tg;
            __half2 w0 = __floats2half2_rn(W2[(long)k0 * HIDN + n],
                                           W2[(long)(k0 + 1) * HIDN + n]);
            __half2 w1 = __floats2half2_rn(W2[(long)(k0 + 8) * HIDN + n],
                                           W2[(long)(k0 + 9) * HIDN + n]);
            g_W2f[id] = make_uint2(*(uint32_t*)&w0, *(uint32_t*)&w1);
        }
    }
}

// ---------------------------------------------------------------------------
// h_loc = lf @ W1[D:]  (6272 x 512 @ 512 x 256), fp32 SGEMM (exact)
// ---------------------------------------------------------------------------
__global__ __launch_bounds__(256) void hloc_kernel(const float* __restrict__ LF,
                                                   const float* __restrict__ W1loc) {
    __shared__ float As[64][33];
    __shared__ float Bs[32][256];
    const int j0  = blockIdx.x * 64;
    const int tid = threadIdx.x;
    const int tm  = tid >> 5;
    const int tn  = tid & 31;
    const int am  = tid & 63;
    const int akq = tid >> 6;
    const int j   = j0 + am;
    const int n_  = j / HW2;
    const int pos = j % HW2;
    const long abase = (long)n_ * CLOC * HW2 + pos;
    const int bn4 = tid & 63;
    const int bkq = tid >> 6;

    float acc[8][8];
    #pragma unroll
    for (int a = 0; a < 8; a++)
        #pragma unroll
        for (int b = 0; b < 8; b++) acc[a][b] = 0.f;

    for (int kc = 0; kc < CLOC; kc += 32) {
        #pragma unroll
        for (int r = 0; r < 8; r++) {
            int k = akq * 8 + r;
            As[am][k] = LF[abase + (long)(kc + k) * HW2];
        }
        #pragma unroll
        for (int r = 0; r < 8; r++) {
            int k = bkq + 4 * r;
            *(float4*)&Bs[k][bn4 * 4] = *(const float4*)&W1loc[(kc + k) * HIDN + bn4 * 4];
        }
        __syncthreads();
        #pragma unroll
        for (int k = 0; k < 32; k++) {
            float a[8];
            #pragma unroll
            for (int im = 0; im < 8; im++) a[im] = As[tm * 8 + im][k];
            float4 b0 = *(float4*)&Bs[k][tn * 4];
            float4 b1 = *(float4*)&Bs[k][128 + tn * 4];
            #pragma unroll
            for (int im = 0; im < 8; im++) {
                acc[im][0] += a[im] * b0.x; acc[im][1] += a[im] * b0.y;
                acc[im][2] += a[im] * b0.z; acc[im][3] += a[im] * b0.w;
                acc[im][4] += a[im] * b1.x; acc[im][5] += a[im] * b1.y;
                acc[im][6] += a[im] * b1.z; acc[im][7] += a[im] * b1.w;
            }
        }
        __syncthreads();
    }
    #pragma unroll
    for (int im = 0; im < 8; im++) {
        int m = j0 + tm * 8 + im;
        float4 v0 = make_float4(acc[im][0], acc[im][1], acc[im][2], acc[im][3]);
        float4 v1 = make_float4(acc[im][4], acc[im][5], acc[im][6], acc[im][7]);
        *(float4*)&g_hloc[m * HIDN + tn * 4]       = v0;
        *(float4*)&g_hloc[m * HIDN + 128 + tn * 4] = v1;
    }
}

// ---------------------------------------------------------------------------
// score kernel: fp16 m16n8k16 mma.sync, 512 threads / 16 warps (4m x 4n),
// warp tile 32m x 64n. Double-buffered, cp.async-pipelined. B fragments are
// pre-packed (g_W2f) so each thread's (b0,b1) is one conflict-free LDS.64.
// ---------------------------------------------------------------------------
#define AS_STRH  72                                 // halves per A row (36 words)
#define AS_BYTES (128 * AS_STRH * 2)                // 18432
#define BS_BYTES 32768                              // 4 ksteps x 8192 B, frag order
#define AS_OFF   0
#define BS_OFF   (2 * AS_BYTES)                     // 36864
#define B2_OFF   (BS_OFF + 2 * BS_BYTES)            // 102400
#define W3_OFF   (B2_OFF + 1024)
#define RED_OFF  (W3_OFF + 1024)
#define SM_TOTAL (RED_OFF + 128 * 4 * 4)            // 106496

__global__ __launch_bounds__(512, 1) void score_mma(const float* __restrict__ b2,
                                                    const float* __restrict__ W3,
                                                    const float* __restrict__ b3p) {
    extern __shared__ char smem[];
    float* b2s = (float*)(smem + B2_OFF);
    float* w3s = (float*)(smem + W3_OFF);
    float* red = (float*)(smem + RED_OFF);
    const uint32_t sbase = smem_u32(smem);

    const int tid = threadIdx.x;
    const int wid = tid >> 5, lid = tid & 31;
    const int g   = lid >> 2, tig = lid & 3;
    const int j0  = blockIdx.x * 128;
    const int i   = blockIdx.y;
    const int m0w = (wid & 3) * 32;                  // warp m-base (4 groups)
    const int nw  = wid >> 2;                        // warp n-index 0..3
    const int n0w = nw * 64;

    if (tid < 256) { b2s[tid] = b2[tid]; w3s[tid] = W3[tid]; }

    // fill-phase thread mappings (512 threads)
    const int k4   = tid & 15;                       // A: halves [k4*4 .. k4*4+3]
    const int mrow = tid >> 4;                       // A rows: mrow + r*32, r<4

    const float* hl = g_hloc + (long)j0 * HIDN;
    const float* gb = g_hglb + i * HIDN;

    float acc[2][8][4];
    #pragma unroll
    for (int mt = 0; mt < 2; mt++)
        #pragma unroll
        for (int nt = 0; nt < 8; nt++)
            #pragma unroll
            for (int q = 0; q < 4; q++) acc[mt][nt][q] = 0.f;

    // ---- initial fill: chunk 0 into buffer 0 ----
    {
        float4 gv = *(const float4*)(gb + k4 * 4);
        __half* As0 = (__half*)(smem + AS_OFF);
        #pragma unroll
        for (int r = 0; r < 4; r++) {
            int m = mrow + r * 32;
            float4 v = *(const float4*)(hl + (long)m * HIDN + k4 * 4);
            __half2 h01 = __floats2half2_rn(fmaxf(v.x + gv.x, 0.f), fmaxf(v.y + gv.y, 0.f));
            __half2 h23 = __floats2half2_rn(fmaxf(v.z + gv.z, 0.f), fmaxf(v.w + gv.w, 0.f));
            uint2 pk = make_uint2(*(uint32_t*)&h01, *(uint32_t*)&h23);
            *(uint2*)(As0 + m * AS_STRH + k4 * 4) = pk;
        }
        const char* bsrc = (const char*)g_W2f;
        #pragma unroll
        for (int r = 0; r < 4; r++) {
            int off = (tid + r * 512) * 16;
            cpa16(sbase + BS_OFF + off, bsrc + off);
        }
        CPA_COMMIT();
        CPA_WAIT0();
        __syncthreads();
    }

    for (int c = 0; c < 4; c++) {
        const int pb = c & 1, nb = pb ^ 1;
        const uint32_t* AsU = (const uint32_t*)(smem + AS_OFF + pb * AS_BYTES);
        const uint2*    BsP = (const uint2*)(smem + BS_OFF + pb * BS_BYTES);

        // ---- prefetch next chunk: A -> regs (LDG), B -> smem (cp.async) ----
        float4 areg[4];
        float4 gvn;
        if (c < 3) {
            const int kb = (c + 1) * 64;
            gvn = *(const float4*)(gb + kb + k4 * 4);
            #pragma unroll
            for (int r = 0; r < 4; r++) {
                int m = mrow + r * 32;
                areg[r] = *(const float4*)(hl + (long)m * HIDN + kb + k4 * 4);
            }
            const char* bsrc = (const char*)g_W2f + (c + 1) * BS_BYTES;
            #pragma unroll
            for (int r = 0; r < 4; r++) {
                int off = (tid + r * 512) * 16;
                cpa16(sbase + BS_OFF + nb * BS_BYTES + off, bsrc + off);
            }
            CPA_COMMIT();
        }

        // ---- mma phase: 4 k16 steps per 64-k chunk ----
        #pragma unroll
        for (int kk = 0; kk < 4; kk++) {
            const int kw = kk * 8;                   // word offset in A row
            uint32_t a[2][4];
            #pragma unroll
            for (int mt = 0; mt < 2; mt++) {
                int mr = m0w + mt * 16 + g;
                a[mt][0] = AsU[mr * 36 + kw + tig];
                a[mt][1] = AsU[(mr + 8) * 36 + kw + tig];
                a[mt][2] = AsU[mr * 36 + kw + tig + 4];
                a[mt][3] = AsU[(mr + 8) * 36 + kw + tig + 4];
            }
            #pragma unroll
            for (int nt = 0; nt < 8; nt++) {
                uint2 bw = BsP[((kk * 4 + nw) * 8 + nt) * 32 + lid];
                mma16(acc[0][nt], a[0], bw.x, bw.y);
                mma16(acc[1][nt], a[1], bw.x, bw.y);
            }
        }

        // ---- store prefetched A into next buffer; wait B; barrier ----
        if (c < 3) {
            __half* AsN = (__half*)(smem + AS_OFF + nb * AS_BYTES);
            #pragma unroll
            for (int r = 0; r < 4; r++) {
                int m = mrow + r * 32;
                __half2 h01 = __floats2half2_rn(fmaxf(areg[r].x + gvn.x, 0.f),
                                                fmaxf(areg[r].y + gvn.y, 0.f));
                __half2 h23 = __floats2half2_rn(fmaxf(areg[r].z + gvn.z, 0.f),
                                                fmaxf(areg[r].w + gvn.w, 0.f));
                uint2 pk = make_uint2(*(uint32_t*)&h01, *(uint32_t*)&h23);
                *(uint2*)(AsN + m * AS_STRH + k4 * 4) = pk;
            }
            CPA_WAIT0();
            __syncthreads();
        }
    }

    // ---- epilogue: relu(acc + b2) . W3, reduce n across lanes/warps ----
    #pragma unroll
    for (int mt = 0; mt < 2; mt++) {
        float s0 = 0.f, s1 = 0.f;
        #pragma unroll
        for (int nt = 0; nt < 8; nt++) {
            int n = n0w + nt * 8 + 2 * tig;
            float w0 = w3s[n], w1 = w3s[n + 1];
            float c0 = b2s[n], c1 = b2s[n + 1];
            s0 += fmaxf(acc[mt][nt][0] + c0, 0.f) * w0
                + fmaxf(acc[mt][nt][1] + c1, 0.f) * w1;
            s1 += fmaxf(acc[mt][nt][2] + c0, 0.f) * w0
                + fmaxf(acc[mt][nt][3] + c1, 0.f) * w1;
        }
        s0 += __shfl_xor_sync(0xffffffffu, s0, 1);
        s0 += __shfl_xor_sync(0xffffffffu, s0, 2);
        s1 += __shfl_xor_sync(0xffffffffu, s1, 1);
        s1 += __shfl_xor_sync(0xffffffffu, s1, 2);
        if (tig == 0) {
            red[(m0w + mt * 16 + g) * 4 + nw]     = s0;
            red[(m0w + mt * 16 + g + 8) * 4 + nw] = s1;
        }
    }
    __syncthreads();
    if (tid < 128) {
        float s = red[tid * 4] + red[tid * 4 + 1] + red[tid * 4 + 2] + red[tid * 4 + 3];
        g_scores[i * NHW + j0 + tid] = s + b3p[0];
    }
}

// ---------------------------------------------------------------------------
// finalize (1024 threads per row)
// ---------------------------------------------------------------------------
__global__ __launch_bounds__(1024) void finalize_kernel(float* __restrict__ out) {
    const int i   = blockIdx.x;
    const int tid = threadIdx.x;
    __shared__ float red[1024];
    const float* row = g_scores + i * NHW;

    float mx = -1e30f;
    for (int jj = tid; jj < NHW; jj += 1024) mx = fmaxf(mx, row[jj]);
    red[tid] = mx;
    __syncthreads();
    for (int s = 512; s; s >>= 1) {
        if (tid < s) red[tid] = fmaxf(red[tid], red[tid + s]);
        __syncthreads();
    }
    mx = red[0];
    __syncthreads();

    const int lo = i * HW2, hi = lo + HW2;
    float sum = 0.f;
    for (int jj = tid; jj < NHW; jj += 1024) {
        if (jj < lo || jj >= hi) sum += __expf(row[jj] - mx);
    }
    red[tid] = sum;
    __syncthreads();
    for (int s = 512; s; s >>= 1) {
        if (tid < s) red[tid] += red[tid + s];
        __syncthreads();
    }
    const float neg_mean = red[0] / (float)(NHW - HW2) + EPSC;
    const float lg = __logf(neg_mean);

    for (int p = tid; p < HW2; p += 1024)
        out[i * HW2 + p] = row[lo + p] - mx - lg;
}

// ---------------------------------------------------------------------------
extern "C" void kernel_launch(void* const* d_in, const int* in_sizes, int n_in,
                              void* d_out, int out_size) {
    const float* LF = (const float*)d_in[0];
    const float* GF = (const float*)d_in[1];
    const float* W1 = (const float*)d_in[2];
    const float* b1 = (const float*)d_in[3];
    const float* W2 = (const float*)d_in[4];
    const float* b2 = (const float*)d_in[5];
    const float* W3 = (const float*)d_in[6];
    const float* b3 = (const float*)d_in[7];
    float* out = (float*)d_out;

    cudaFuncSetAttribute(score_mma, cudaFuncAttributeMaxDynamicSharedMemorySize, SM_TOTAL);

    prep_kernel<<<NB + 8, 1024>>>(GF, W1, b1, W2);
    hloc_kernel<<<NHW / 64, 256>>>(LF, W1 + (long)DGLB * HIDN);
    score_mma<<<dim3(NHW / 128, NB), 512, SM_TOTAL>>>(b2, W3, b3);
    finalize_kernel<<<NB, 1024>>>(out);
}